// round 14
// baseline (speedup 1.0000x reference)
#include <cuda_runtime.h>

#define NN 512
#define CC 64
#define HH 256
#define EPSF 1e-5f

typedef unsigned long long u64;

// ---------------- packed f32x2 helpers (verified on sm_103a) ----------------
__device__ __forceinline__ u64 pk(float lo, float hi) {
    u64 r; asm("mov.b64 %0,{%1,%2};" : "=l"(r) : "f"(lo), "f"(hi)); return r;
}
__device__ __forceinline__ void unpk(u64 v, float& lo, float& hi) {
    asm("mov.b64 {%0,%1},%2;" : "=f"(lo), "=f"(hi) : "l"(v));
}
__device__ __forceinline__ u64 add2(u64 a, u64 b) {
    u64 r; asm("add.rn.f32x2 %0,%1,%2;" : "=l"(r) : "l"(a), "l"(b)); return r;
}
__device__ __forceinline__ u64 fma2(u64 a, u64 b, u64 c) {
    u64 r; asm("fma.rn.f32x2 %0,%1,%2,%3;" : "=l"(r) : "l"(a), "l"(b), "l"(c)); return r;
}
__device__ __forceinline__ float ex2f(float x) {
    float r; asm("ex2.approx.f32 %0,%1;" : "=f"(r) : "f"(x)); return r;
}
__device__ __forceinline__ float warp_sum(float x) {
#pragma unroll
    for (int off = 16; off > 0; off >>= 1)
        x += __shfl_xor_sync(0xffffffffu, x, off);
    return x;
}

// ---------------- scratch (device globals) ----------------
__device__ float g_T[2][NN][768];
__device__ float g_RA [NN*HH];
__device__ float g_RB [NN*HH];
__device__ float g_A1M[NN*HH];
__device__ float g_A2P[NN*HH];
__device__ float g_B1P[NN*HH];
__device__ float g_B2M[NN*HH];
__device__ float g_SA[NN];
__device__ float g_SB[NN];
__device__ float g_QA[NN];
__device__ float g_QB[NN];
__device__ float g_DA[NN];
__device__ float g_DB[NN];
__device__ float g_CW, g_CWG, g_CWB;

// ---------------------------------------------------------------------------
// Stage 1: GEMM, 32x32 tiles, 128 threads, pipelined k-loop. (proven)
// ---------------------------------------------------------------------------
__global__ __launch_bounds__(128) void gemm_pre_kernel(
    const float* __restrict__ xl, const float* __restrict__ xr,
    const float* __restrict__ W1)
{
    __shared__ float Xs[64][36];
    __shared__ float Ws[64][36];

    const int z  = blockIdx.z;
    const float* X = z ? xr : xl;
    const int m0 = blockIdx.x * 32;
    const int n0 = blockIdx.y * 32;
    const int sel = n0 >> 8;
    const int h0  = n0 & 255;
    const float* Wbase = W1 + ((2 * sel + z) * 64) * HH + h0;

    const int t = threadIdx.x;
    {
        int f = t & 63, i2 = t >> 6;
#pragma unroll
        for (int ii = 0; ii < 32; ii += 2)
            Xs[f][i2 + ii] = X[(m0 + i2 + ii) * CC + f];
    }
    {
        int n = t & 31, f0 = t >> 5;
#pragma unroll
        for (int ff = 0; ff < 64; ff += 4)
            Ws[f0 + ff][n] = Wbase[(f0 + ff) * HH + n];
    }
    __syncthreads();

    const int tx = t & 7, ty = t >> 3;
    u64 acc[2][2] = {};
    float2 xa = *reinterpret_cast<const float2*>(&Xs[0][2 * ty]);
    ulonglong2 wb = *reinterpret_cast<const ulonglong2*>(&Ws[0][4 * tx]);
#pragma unroll 16
    for (int k = 0; k < 64; k++) {
        const int kn = (k + 1) & 63;
        float2 xan = *reinterpret_cast<const float2*>(&Xs[kn][2 * ty]);
        ulonglong2 wbn = *reinterpret_cast<const ulonglong2*>(&Ws[kn][4 * tx]);
        u64 x0 = pk(xa.x, xa.x), x1 = pk(xa.y, xa.y);
        acc[0][0] = fma2(x0, wb.x, acc[0][0]);
        acc[0][1] = fma2(x0, wb.y, acc[0][1]);
        acc[1][0] = fma2(x1, wb.x, acc[1][0]);
        acc[1][1] = fma2(x1, wb.y, acc[1][1]);
        xa = xan; wb = wbn;
    }
#pragma unroll
    for (int r = 0; r < 2; r++) {
        float a, b, c, d;
        unpk(acc[r][0], a, b);
        unpk(acc[r][1], c, d);
        *reinterpret_cast<float4*>(&g_T[z][m0 + 2 * ty + r][n0 + 4 * tx]) =
            make_float4(a, b, c, d);
    }
}

// ---------------------------------------------------------------------------
// Stage 2: combine shifts + b1 into RA/RB (+masked parts), row stats
// S (sum), Q (sum sq), D (sum w2*gamma*r), and W2 constants. (proven R13)
// ---------------------------------------------------------------------------
__global__ __launch_bounds__(256) void combine_kernel(
    const float* __restrict__ b1, const float* __restrict__ W2,
    const float* __restrict__ gamma, const float* __restrict__ beta)
{
    __shared__ float red[8][6];
    __shared__ float redc[8][3];
    const int i = blockIdx.x, h = threadIdx.x;
    const int lane = h & 31, w = h >> 5;

    float a0  = g_T[0][i][h];
    float a1m = (i > 0)      ? g_T[0][i - 1][256 + h] : 0.f;
    float a2p = (i < NN - 1) ? g_T[0][i + 1][512 + h] : 0.f;
    float ra  = a0 + b1[h] + a1m + a2p;
    g_A1M[i * HH + h] = a1m;
    g_A2P[i * HH + h] = a2p;
    g_RA [i * HH + h] = ra;

    float b0  = g_T[1][i][h];
    float b1p = (i < NN - 1) ? g_T[1][i + 1][256 + h] : 0.f;
    float b2m = (i > 0)      ? g_T[1][i - 1][512 + h] : 0.f;
    float rb  = b0 + b1p + b2m;
    g_B1P[i * HH + h] = b1p;
    g_B2M[i * HH + h] = b2m;
    g_RB [i * HH + h] = rb;

    const float w2h = W2[h];
    const float wg  = w2h * gamma[h];

    float sa = warp_sum(ra);
    float sb = warp_sum(rb);
    float qa = warp_sum(ra * ra);
    float qb = warp_sum(rb * rb);
    float da = warp_sum(wg * ra);
    float db = warp_sum(wg * rb);
    if (lane == 0) {
        red[w][0] = sa; red[w][1] = sb; red[w][2] = qa;
        red[w][3] = qb; red[w][4] = da; red[w][5] = db;
    }
    if (i == 0) {
        float cw  = warp_sum(w2h);
        float cwg = warp_sum(wg);
        float cwb = warp_sum(w2h * beta[h]);
        if (lane == 0) { redc[w][0] = cw; redc[w][1] = cwg; redc[w][2] = cwb; }
    }
    __syncthreads();
    if (h == 0) {
        float v[6] = {};
#pragma unroll
        for (int k = 0; k < 8; k++)
#pragma unroll
            for (int m = 0; m < 6; m++) v[m] += red[k][m];
        g_SA[i] = v[0]; g_SB[i] = v[1];
        g_QA[i] = v[2]; g_QB[i] = v[3];
        g_DA[i] = v[4]; g_DB[i] = v[5];
        if (i == 0) {
            float cw = 0.f, cwg = 0.f, cwb = 0.f;
#pragma unroll
            for (int k = 0; k < 8; k++) {
                cw += redc[k][0]; cwg += redc[k][1]; cwb += redc[k][2];
            }
            g_CW = cw; g_CWG = cwg; g_CWB = cwb;
        }
    }
}

// ---------------------------------------------------------------------------
// Stage 3: fused pair kernel. Blocks 0..255: 32x32 tile, 128 threads,
// R=8 rows/thread (warp w -> rows 8w..8w+7, lane = j). 8-way ILP per thread.
//   pass1: cross-dot -> variance (sq = QA + QB + 2X).
//   pass2: nonlinear CELU residual u = 2^m' - ln2*m' (m'=min(h',0));
//          linear part = rs*(DA+DB) + nm*CWG (+ consts).
// Blocks 256..287: border fixup (4 warps x 16 cells). Main tiles skip borders.
// ---------------------------------------------------------------------------
#define SA_OFF   0
#define SB_OFF   32768
#define SGB_OFF  66560
#define SW_OFF   68608
#define SSA_OFF  69632
#define SSB_OFF  69760
#define SQA_OFF  69888
#define SQB_OFF  70016
#define SDA_OFF  70144
#define SDB_OFF  70272
#define SMEM_SZ  70400

__global__ __launch_bounds__(128) void pair_fused_kernel(
    const float* __restrict__ gamma, const float* __restrict__ beta,
    const float* __restrict__ W2, const float* __restrict__ b2,
    float* __restrict__ out)
{
    const int t = threadIdx.x;
    const int lane = t & 31, w = t >> 5;

    if (blockIdx.x >= 256) {
        // ================= fixup path (4 warps x 16 cells) =================
        const int fb = blockIdx.x - 256;           // 0..31
#pragma unroll 1
        for (int c = 0; c < 16; c++) {
            const int gw = fb * 4 + w + 128 * c;   // 0..2047
            const int side = gw >> 9, pos = gw & 511;
            int i, j;
            if      (side == 0) { i = 0;      j = pos; }
            else if (side == 1) { i = NN - 1; j = pos; }
            else if (side == 2) { i = pos;    j = 0; }
            else                { i = pos;    j = NN - 1; }

            const bool mi0 = (i == 0), mi1 = (i == NN - 1);
            const bool mj0 = (j == 0), mj1 = (j == NN - 1);
            const float4 z4 = make_float4(0.f, 0.f, 0.f, 0.f);

            const float4* RA4 = reinterpret_cast<const float4*>(g_RA)  + i * 64;
            const float4* RB4 = reinterpret_cast<const float4*>(g_RB)  + j * 64;
            const float4* BP4 = reinterpret_cast<const float4*>(g_B1P) + j * 64;
            const float4* BM4 = reinterpret_cast<const float4*>(g_B2M) + j * 64;
            const float4* AP4 = reinterpret_cast<const float4*>(g_A2P) + i * 64;
            const float4* AM4 = reinterpret_cast<const float4*>(g_A1M) + i * 64;

            float s[8], gm[8], bt[8], w2r[8];
#pragma unroll
            for (int half = 0; half < 2; half++) {
                int idx = lane + 32 * half;
                float4 ra = RA4[idx];
                float4 rb = RB4[idx];
                float4 c1 = mi0 ? BP4[idx] : z4;
                float4 c2 = mi1 ? BM4[idx] : z4;
                float4 c3 = mj0 ? AP4[idx] : z4;
                float4 c4 = mj1 ? AM4[idx] : z4;
                int o = 4 * half;
                s[o + 0] = ra.x + rb.x - c1.x - c2.x - c3.x - c4.x;
                s[o + 1] = ra.y + rb.y - c1.y - c2.y - c3.y - c4.y;
                s[o + 2] = ra.z + rb.z - c1.z - c2.z - c3.z - c4.z;
                s[o + 3] = ra.w + rb.w - c1.w - c2.w - c3.w - c4.w;
                float4 gv = reinterpret_cast<const float4*>(gamma)[idx];
                float4 bv = reinterpret_cast<const float4*>(beta )[idx];
                float4 wv = reinterpret_cast<const float4*>(W2   )[idx];
                gm[o] = gv.x; gm[o+1] = gv.y; gm[o+2] = gv.z; gm[o+3] = gv.w;
                bt[o] = bv.x; bt[o+1] = bv.y; bt[o+2] = bv.z; bt[o+3] = bv.w;
                w2r[o] = wv.x; w2r[o+1] = wv.y; w2r[o+2] = wv.z; w2r[o+3] = wv.w;
            }

            float sum = ((s[0] + s[1]) + (s[2] + s[3])) + ((s[4] + s[5]) + (s[6] + s[7]));
            float sq  = fmaf(s[0], s[0], s[1] * s[1]);
            sq = fmaf(s[2], s[2], fmaf(s[3], s[3], sq));
            sq = fmaf(s[4], s[4], sq);
            sq = fmaf(s[5], s[5], sq);
            sq = fmaf(s[6], s[6], fmaf(s[7], s[7], sq));
            sum = warp_sum(sum);
            sq  = warp_sum(sq);

            float mu  = sum * (1.f / 256.f);
            float var = fmaf(sq, 1.f / 256.f, -mu * mu);
            float rs  = rsqrtf(var + EPSF);
            float nm  = -mu * rs;
            float acc = 0.f;
#pragma unroll
            for (int k = 0; k < 8; k++) {
                float hn = fmaf(fmaf(s[k], rs, nm), gm[k], bt[k]);
                float e  = __expf(fminf(hn, 0.f)) - 1.f;
                float v  = fmaxf(hn, 0.f) + e;
                acc = fmaf(v, w2r[k], acc);
            }
            acc = warp_sum(acc);
            if (lane == 0) out[i * NN + j] = acc + b2[0];
        }
        return;
    }

    // ================= main tile path (32 x 32 cells, R=8) =================
    extern __shared__ __align__(16) char smem_raw[];
    u64 (*sA)[128] = reinterpret_cast<u64(*)[128]>(smem_raw + SA_OFF);
    u64 (*sB)[33]  = reinterpret_cast<u64(*)[33]>(smem_raw + SB_OFF);
    u64 (*sGB)[2]  = reinterpret_cast<u64(*)[2]>(smem_raw + SGB_OFF);
    u64* sW  = reinterpret_cast<u64*>(smem_raw + SW_OFF);
    float* sSA = reinterpret_cast<float*>(smem_raw + SSA_OFF);
    float* sSB = reinterpret_cast<float*>(smem_raw + SSB_OFF);
    float* sQA = reinterpret_cast<float*>(smem_raw + SQA_OFF);
    float* sQB = reinterpret_cast<float*>(smem_raw + SQB_OFF);
    float* sDA = reinterpret_cast<float*>(smem_raw + SDA_OFF);
    float* sDB = reinterpret_cast<float*>(smem_raw + SDB_OFF);

    const int i0 = (blockIdx.x >> 4) * 32, j0 = (blockIdx.x & 15) * 32;
    const float L2E  = 1.4426950408889634f;
    const float MLN2 = -0.6931471805599453f;

    {   // sA: 32 rows x 128 u64 = 4096 u64, 32 per thread
        const u64* gA = reinterpret_cast<const u64*>(g_RA) + i0 * 128;
#pragma unroll
        for (int k = 0; k < 32; k++) {
            int idx = t + 128 * k;
            sA[idx >> 7][idx & 127] = gA[idx];
        }
    }
    {   // sB transposed: sB[c2][j]
        const u64* gB = reinterpret_cast<const u64*>(g_RB) + j0 * 128;
        int j = t >> 2, part = t & 3;
#pragma unroll
        for (int k = 0; k < 32; k++) {
            int c2 = part + 4 * k;
            sB[c2][j] = gB[j * 128 + c2];
        }
    }
    {   // const tables (all 128 threads)
        float2 gv = reinterpret_cast<const float2*>(gamma)[t];
        float2 bv = reinterpret_cast<const float2*>(beta)[t];
        float2 wv = reinterpret_cast<const float2*>(W2)[t];
        sGB[t][0] = pk(gv.x * L2E, gv.y * L2E);
        sGB[t][1] = pk(bv.x * L2E, bv.y * L2E);
        sW [t]    = pk(wv.x, wv.y);
    }
    if (t < 32)      { sSA[t] = g_SA[i0 + t];      sDA[t] = g_DA[i0 + t]; }
    else if (t < 64) { sSB[t - 32] = g_SB[j0 + t - 32]; sDB[t - 32] = g_DB[j0 + t - 32]; }
    else if (t < 96) { sQA[t - 64] = g_QA[i0 + t - 64]; }
    else             { sQB[t - 96] = g_QB[j0 + t - 96]; }
    const float CWG  = g_CWG;
    const float CADD = b2[0] - g_CW + g_CWB;
    __syncthreads();

    const int r0 = 8 * w;

    // ---- pass 1: cross-dot X[r] = sum_c RA*RB (packed, 8-way ILP) ----
    u64 xd[8] = {};
#pragma unroll 4
    for (int c2 = 0; c2 < 128; c2++) {
        u64 bv = sB[c2][lane];
#pragma unroll
        for (int r = 0; r < 8; r++)
            xd[r] = fma2(sA[r0 + r][c2], bv, xd[r]);
    }
    u64 rs2[8], nm2[8];
#pragma unroll
    for (int r = 0; r < 8; r++) {
        float xl_, xh_; unpk(xd[r], xl_, xh_);
        float sq  = sQA[r0 + r] + sQB[lane] + 2.f * (xl_ + xh_);
        float sum = sSA[r0 + r] + sSB[lane];
        float mu  = sum * (1.f / 256.f);
        float var = fmaf(sq, 1.f / 256.f, -mu * mu);
        float rs  = rsqrtf(var + EPSF);
        float nm  = -mu * rs;
        rs2[r] = pk(rs, rs);
        nm2[r] = pk(nm, nm);
    }

    // ---- pass 2: CELU residual u = 2^m' - ln2*m', accumulate w2*u ----
    u64 ae[8] = {};
#pragma unroll 2
    for (int c2 = 0; c2 < 128; c2++) {
        u64 bv = sB[c2][lane];
        ulonglong2 gb = *reinterpret_cast<const ulonglong2*>(sGB[c2]);
        u64 wv = sW[c2];
#pragma unroll
        for (int r = 0; r < 8; r++) {
            u64 s = add2(sA[r0 + r][c2], bv);
            u64 h = fma2(fma2(s, rs2[r], nm2[r]), gb.x, gb.y);
            float hl, hh; unpk(h, hl, hh);
            float ml = fminf(hl, 0.f);
            float mh = fminf(hh, 0.f);
            float ul = fmaf(MLN2, ml, ex2f(ml));
            float uh = fmaf(MLN2, mh, ex2f(mh));
            ae[r] = fma2(pk(ul, uh), wv, ae[r]);
        }
    }

    const int gj = j0 + lane;
    const bool jint = (gj != 0) && (gj != NN - 1);
#pragma unroll
    for (int r = 0; r < 8; r++) {
        int gi = i0 + r0 + r;
        if (jint && gi != 0 && gi != NN - 1) {
            float rs_, nm_, d0, d1;
            unpk(rs2[r], rs_, d0);
            unpk(nm2[r], nm_, d1);
            float dd = sDA[r0 + r] + sDB[lane];
            float lin = fmaf(rs_, dd, nm_ * CWG);
            float a, b; unpk(ae[r], a, b);
            out[gi * NN + gj] = lin + (a + b) + CADD;
        }
    }
}

// ---------------------------------------------------------------------------
extern "C" void kernel_launch(void* const* d_in, const int* in_sizes, int n_in,
                              void* d_out, int out_size)
{
    const float* xl    = (const float*)d_in[0];
    const float* xr    = (const float*)d_in[1];
    const float* W1    = (const float*)d_in[2];
    const float* b1    = (const float*)d_in[3];
    const float* gamma = (const float*)d_in[4];
    const float* beta  = (const float*)d_in[5];
    const float* W2    = (const float*)d_in[6];
    const float* b2    = (const float*)d_in[7];
    float* out = (float*)d_out;

    static bool attr_set = false;
    if (!attr_set) {
        cudaFuncSetAttribute(pair_fused_kernel,
                             cudaFuncAttributeMaxDynamicSharedMemorySize, SMEM_SZ);
        attr_set = true;
    }

    dim3 gpre(16, 24, 2);
    gemm_pre_kernel<<<gpre, 128>>>(xl, xr, W1);
    combine_kernel<<<NN, 256>>>(b1, W2, gamma, beta);
    pair_fused_kernel<<<256 + 32, 128, SMEM_SZ>>>(gamma, beta, W2, b2, out);
}

// round 15
// speedup vs baseline: 1.1412x; 1.1412x over previous
#include <cuda_runtime.h>

#define NN 512
#define CC 64
#define HH 256
#define EPSF 1e-5f

typedef unsigned long long u64;

// ---------------- packed f32x2 helpers (verified on sm_103a) ----------------
__device__ __forceinline__ u64 pk(float lo, float hi) {
    u64 r; asm("mov.b64 %0,{%1,%2};" : "=l"(r) : "f"(lo), "f"(hi)); return r;
}
__device__ __forceinline__ void unpk(u64 v, float& lo, float& hi) {
    asm("mov.b64 {%0,%1},%2;" : "=f"(lo), "=f"(hi) : "l"(v));
}
__device__ __forceinline__ u64 add2(u64 a, u64 b) {
    u64 r; asm("add.rn.f32x2 %0,%1,%2;" : "=l"(r) : "l"(a), "l"(b)); return r;
}
__device__ __forceinline__ u64 fma2(u64 a, u64 b, u64 c) {
    u64 r; asm("fma.rn.f32x2 %0,%1,%2,%3;" : "=l"(r) : "l"(a), "l"(b), "l"(c)); return r;
}
__device__ __forceinline__ float ex2f(float x) {
    float r; asm("ex2.approx.f32 %0,%1;" : "=f"(r) : "f"(x)); return r;
}
__device__ __forceinline__ float warp_sum(float x) {
#pragma unroll
    for (int off = 16; off > 0; off >>= 1)
        x += __shfl_xor_sync(0xffffffffu, x, off);
    return x;
}

// ---------------- scratch (device globals) ----------------
__device__ float g_T[2][NN][768];
__device__ float g_RA [NN*HH];
__device__ float g_RB [NN*HH];
__device__ float g_A1M[NN*HH];
__device__ float g_A2P[NN*HH];
__device__ float g_B1P[NN*HH];
__device__ float g_B2M[NN*HH];
__device__ float g_SA[NN];
__device__ float g_SB[NN];
__device__ float g_QA[NN];
__device__ float g_QB[NN];
__device__ float g_CW;

// ---------------------------------------------------------------------------
// Stage 1: tiled GEMM, 64x64 tiles, 256 threads (R2-proven best: 8.8us).
// M=512, N=768, K=64, two batches (xl / xr). Grid (8, 12, 2).
// ---------------------------------------------------------------------------
__global__ __launch_bounds__(256) void gemm_pre_kernel(
    const float* __restrict__ xl, const float* __restrict__ xr,
    const float* __restrict__ W1)
{
    __shared__ float Xs[64][68];  // [k][m], padded
    __shared__ float Ws[64][68];  // [k][n], padded

    const int z  = blockIdx.z;
    const float* X = z ? xr : xl;
    const int m0 = blockIdx.x * 64;
    const int n0 = blockIdx.y * 64;
    const int sel = n0 >> 8;
    const int h0  = n0 & 255;
    const float* Wbase = W1 + ((2 * sel + z) * 64) * HH + h0;

    const int t = threadIdx.x;
    {   // load X transposed: Xs[f][i] = X[(m0+i)*64 + f]
        int f = t & 63, i0 = t >> 6;
#pragma unroll
        for (int ii = 0; ii < 64; ii += 4)
            Xs[f][i0 + ii] = X[(m0 + i0 + ii) * CC + f];
    }
    {   // load W: Ws[f][n] = Wbase[f*HH + n]
        int n = t & 63, f0 = t >> 6;
#pragma unroll
        for (int ff = 0; ff < 64; ff += 4)
            Ws[f0 + ff][n] = Wbase[(f0 + ff) * HH + n];
    }
    __syncthreads();

    const int tx = t & 15, ty = t >> 4;   // n = n0+4*tx.., m = m0+4*ty..
    float acc[4][4] = {};
#pragma unroll 16
    for (int k = 0; k < 64; k++) {
        float4 xa = *reinterpret_cast<const float4*>(&Xs[k][4 * ty]);
        float4 wb = *reinterpret_cast<const float4*>(&Ws[k][4 * tx]);
        float xr4[4] = {xa.x, xa.y, xa.z, xa.w};
        float wr4[4] = {wb.x, wb.y, wb.z, wb.w};
#pragma unroll
        for (int r = 0; r < 4; r++)
#pragma unroll
            for (int c = 0; c < 4; c++)
                acc[r][c] = fmaf(xr4[r], wr4[c], acc[r][c]);
    }
#pragma unroll
    for (int r = 0; r < 4; r++) {
        float4 v = make_float4(acc[r][0], acc[r][1], acc[r][2], acc[r][3]);
        *reinterpret_cast<float4*>(&g_T[z][m0 + 4 * ty + r][n0 + 4 * tx]) = v;
    }
}

// ---------------------------------------------------------------------------
// Stage 2: combine shifts + b1 into RA/RB (+masked parts), row sums SA/SB,
// row sums-of-squares QA/QB, W2 total. (R9-proven.)
// ---------------------------------------------------------------------------
__global__ __launch_bounds__(256) void combine_kernel(
    const float* __restrict__ b1, const float* __restrict__ W2)
{
    __shared__ float smA[8], smB[8], smW[8], smQA[8], smQB[8];
    const int i = blockIdx.x, h = threadIdx.x;
    const int lane = h & 31, w = h >> 5;

    float a0  = g_T[0][i][h];
    float a1m = (i > 0)      ? g_T[0][i - 1][256 + h] : 0.f;
    float a2p = (i < NN - 1) ? g_T[0][i + 1][512 + h] : 0.f;
    float ra  = a0 + b1[h] + a1m + a2p;
    g_A1M[i * HH + h] = a1m;
    g_A2P[i * HH + h] = a2p;
    g_RA [i * HH + h] = ra;

    float b0  = g_T[1][i][h];
    float b1p = (i < NN - 1) ? g_T[1][i + 1][256 + h] : 0.f;
    float b2m = (i > 0)      ? g_T[1][i - 1][512 + h] : 0.f;
    float rb  = b0 + b1p + b2m;
    g_B1P[i * HH + h] = b1p;
    g_B2M[i * HH + h] = b2m;
    g_RB [i * HH + h] = rb;

    float sa = warp_sum(ra);
    float sb = warp_sum(rb);
    float qa = warp_sum(ra * ra);
    float qb = warp_sum(rb * rb);
    float sw = warp_sum((i == 0) ? W2[h] : 0.f);
    if (lane == 0) { smA[w] = sa; smB[w] = sb; smQA[w] = qa; smQB[w] = qb; smW[w] = sw; }
    __syncthreads();
    if (h == 0) {
        float ta = 0.f, tb = 0.f, tqa = 0.f, tqb = 0.f, tw = 0.f;
#pragma unroll
        for (int k = 0; k < 8; k++) {
            ta += smA[k]; tb += smB[k]; tqa += smQA[k]; tqb += smQB[k]; tw += smW[k];
        }
        g_SA[i] = ta; g_SB[i] = tb;
        g_QA[i] = tqa; g_QB[i] = tqb;
        if (i == 0) g_CW = tw;
    }
}

// ---------------------------------------------------------------------------
// Stage 3: fused pair kernel (R9-proven golden config). Blocks 0..255:
// 32x32 tile, R=4 rows/thread, software-pipelined LDS.
//   pass1: cross-dot X = sum RA*RB (packed); sq = QA + QB + 2X.
//   pass2: LN + CELU (log2e domain) + dot(W2).
// Blocks 256..287: border fixup. Main tiles skip border stores.
// ---------------------------------------------------------------------------
#define SA_OFF   0
#define SB_OFF   32768
#define SGB_OFF  66560
#define SW_OFF   68608
#define SSA_OFF  70656
#define SSB_OFF  70784
#define SQA_OFF  70912
#define SQB_OFF  71040
#define SMEM_SZ  71168

__global__ __launch_bounds__(256, 3) void pair_fused_kernel(
    const float* __restrict__ gamma, const float* __restrict__ beta,
    const float* __restrict__ W2, const float* __restrict__ b2,
    float* __restrict__ out)
{
    const int t = threadIdx.x;
    const int lane = t & 31, w = t >> 5;

    if (blockIdx.x >= 256) {
        // ================= fixup path =================
        const int fb = blockIdx.x - 256;
#pragma unroll 1
        for (int c = 0; c < 8; c++) {
            const int gw = fb * 8 + w + 256 * c;
            const int side = gw >> 9, pos = gw & 511;
            int i, j;
            if      (side == 0) { i = 0;      j = pos; }
            else if (side == 1) { i = NN - 1; j = pos; }
            else if (side == 2) { i = pos;    j = 0; }
            else                { i = pos;    j = NN - 1; }

            const bool mi0 = (i == 0), mi1 = (i == NN - 1);
            const bool mj0 = (j == 0), mj1 = (j == NN - 1);
            const float4 z4 = make_float4(0.f, 0.f, 0.f, 0.f);

            const float4* RA4 = reinterpret_cast<const float4*>(g_RA)  + i * 64;
            const float4* RB4 = reinterpret_cast<const float4*>(g_RB)  + j * 64;
            const float4* BP4 = reinterpret_cast<const float4*>(g_B1P) + j * 64;
            const float4* BM4 = reinterpret_cast<const float4*>(g_B2M) + j * 64;
            const float4* AP4 = reinterpret_cast<const float4*>(g_A2P) + i * 64;
            const float4* AM4 = reinterpret_cast<const float4*>(g_A1M) + i * 64;

            float s[8], gm[8], bt[8], w2r[8];
#pragma unroll
            for (int half = 0; half < 2; half++) {
                int idx = lane + 32 * half;
                float4 ra = RA4[idx];
                float4 rb = RB4[idx];
                float4 c1 = mi0 ? BP4[idx] : z4;
                float4 c2 = mi1 ? BM4[idx] : z4;
                float4 c3 = mj0 ? AP4[idx] : z4;
                float4 c4 = mj1 ? AM4[idx] : z4;
                int o = 4 * half;
                s[o + 0] = ra.x + rb.x - c1.x - c2.x - c3.x - c4.x;
                s[o + 1] = ra.y + rb.y - c1.y - c2.y - c3.y - c4.y;
                s[o + 2] = ra.z + rb.z - c1.z - c2.z - c3.z - c4.z;
                s[o + 3] = ra.w + rb.w - c1.w - c2.w - c3.w - c4.w;
                float4 gv = reinterpret_cast<const float4*>(gamma)[idx];
                float4 bv = reinterpret_cast<const float4*>(beta )[idx];
                float4 wv = reinterpret_cast<const float4*>(W2   )[idx];
                gm[o] = gv.x; gm[o+1] = gv.y; gm[o+2] = gv.z; gm[o+3] = gv.w;
                bt[o] = bv.x; bt[o+1] = bv.y; bt[o+2] = bv.z; bt[o+3] = bv.w;
                w2r[o] = wv.x; w2r[o+1] = wv.y; w2r[o+2] = wv.z; w2r[o+3] = wv.w;
            }

            float sum = ((s[0] + s[1]) + (s[2] + s[3])) + ((s[4] + s[5]) + (s[6] + s[7]));
            float sq  = fmaf(s[0], s[0], s[1] * s[1]);
            sq = fmaf(s[2], s[2], fmaf(s[3], s[3], sq));
            sq = fmaf(s[4], s[4], sq);
            sq = fmaf(s[5], s[5], sq);
            sq = fmaf(s[6], s[6], fmaf(s[7], s[7], sq));
            sum = warp_sum(sum);
            sq  = warp_sum(sq);

            float mu  = sum * (1.f / 256.f);
            float var = fmaf(sq, 1.f / 256.f, -mu * mu);
            float rs  = rsqrtf(var + EPSF);
            float nm  = -mu * rs;
            float acc = 0.f;
#pragma unroll
            for (int k = 0; k < 8; k++) {
                float hn = fmaf(fmaf(s[k], rs, nm), gm[k], bt[k]);
                float e  = __expf(fminf(hn, 0.f)) - 1.f;
                float v  = fmaxf(hn, 0.f) + e;
                acc = fmaf(v, w2r[k], acc);
            }
            acc = warp_sum(acc);
            if (lane == 0) out[i * NN + j] = acc + b2[0];
        }
        return;
    }

    // ================= main tile path =================
    extern __shared__ __align__(16) char smem_raw[];
    u64 (*sA)[128] = reinterpret_cast<u64(*)[128]>(smem_raw + SA_OFF);
    u64 (*sB)[33]  = reinterpret_cast<u64(*)[33]>(smem_raw + SB_OFF);
    u64 (*sGB)[2]  = reinterpret_cast<u64(*)[2]>(smem_raw + SGB_OFF);
    u64 (*sW)[2]   = reinterpret_cast<u64(*)[2]>(smem_raw + SW_OFF);
    float* sSA = reinterpret_cast<float*>(smem_raw + SSA_OFF);
    float* sSB = reinterpret_cast<float*>(smem_raw + SSB_OFF);
    float* sQA = reinterpret_cast<float*>(smem_raw + SQA_OFF);
    float* sQB = reinterpret_cast<float*>(smem_raw + SQB_OFF);

    const int i0 = (blockIdx.x >> 4) * 32, j0 = (blockIdx.x & 15) * 32;
    const float L2E  = 1.4426950408889634f;
    const float IL2E = 0.6931471805599453f;

    {
        const u64* gA = reinterpret_cast<const u64*>(g_RA) + i0 * 128;
#pragma unroll
        for (int k = 0; k < 16; k++) {
            int idx = t + 256 * k;
            sA[idx >> 7][idx & 127] = gA[idx];
        }
    }
    {
        const u64* gB = reinterpret_cast<const u64*>(g_RB) + j0 * 128;
        int j = t >> 3, part = t & 7;
#pragma unroll
        for (int k = 0; k < 16; k++) {
            int c2 = part + 8 * k;
            sB[c2][j] = gB[j * 128 + c2];
        }
    }
    if (t < 128) {
        float2 gv = reinterpret_cast<const float2*>(gamma)[t];
        float2 bv = reinterpret_cast<const float2*>(beta)[t];
        float2 wv = reinterpret_cast<const float2*>(W2)[t];
        sGB[t][0] = pk(gv.x * L2E, gv.y * L2E);
        sGB[t][1] = pk(bv.x * L2E, bv.y * L2E);
        sW [t][0] = pk(wv.x * IL2E, wv.y * IL2E);
        sW [t][1] = pk(wv.x, wv.y);
    } else if (t < 160) {
        sSA[t - 128] = g_SA[i0 + t - 128];
    } else if (t < 192) {
        sSB[t - 160] = g_SB[j0 + t - 160];
    } else if (t < 224) {
        sQA[t - 192] = g_QA[i0 + t - 192];
    } else {
        sQB[t - 224] = g_QB[j0 + t - 224];
    }
    const float CADD = b2[0] - g_CW;
    __syncthreads();

    const int r0 = 4 * w;

    // ---- pass 1: cross-dot X[r] = sum_c RA*RB (packed, pipelined) ----
    u64 xd[4] = {0, 0, 0, 0};
    {
        u64 bv = sB[0][lane];
#pragma unroll 8
        for (int c2 = 0; c2 < 128; c2++) {
            u64 bvn = sB[(c2 + 1) & 127][lane];
#pragma unroll
            for (int r = 0; r < 4; r++)
                xd[r] = fma2(sA[r0 + r][c2], bv, xd[r]);
            bv = bvn;
        }
    }
    u64 rs2[4], nm2[4];
#pragma unroll
    for (int r = 0; r < 4; r++) {
        float xl_, xh_; unpk(xd[r], xl_, xh_);
        float sq  = sQA[r0 + r] + sQB[lane] + 2.f * (xl_ + xh_);
        float sum = sSA[r0 + r] + sSB[lane];
        float mu  = sum * (1.f / 256.f);
        float var = fmaf(sq, 1.f / 256.f, -mu * mu);
        float rs  = rsqrtf(var + EPSF);
        rs2[r] = pk(rs, rs);
        float nm = -mu * rs;
        nm2[r] = pk(nm, nm);
    }

    // ---- pass 2: CELU (log2e domain) + dot(W2), pipelined ----
    u64 am[4] = {0, 0, 0, 0}, ae[4] = {0, 0, 0, 0};
    {
        u64 bv = sB[0][lane];
        ulonglong2 gb = *reinterpret_cast<const ulonglong2*>(sGB[0]);
        ulonglong2 wv = *reinterpret_cast<const ulonglong2*>(sW[0]);
#pragma unroll 4
        for (int c2 = 0; c2 < 128; c2++) {
            const int cn = (c2 + 1) & 127;
            u64 bvn = sB[cn][lane];
            ulonglong2 gbn = *reinterpret_cast<const ulonglong2*>(sGB[cn]);
            ulonglong2 wvn = *reinterpret_cast<const ulonglong2*>(sW[cn]);
#pragma unroll
            for (int r = 0; r < 4; r++) {
                u64 s = add2(sA[r0 + r][c2], bv);
                u64 h = fma2(fma2(s, rs2[r], nm2[r]), gb.x, gb.y);
                float hl, hh; unpk(h, hl, hh);
                float el = ex2f(fminf(hl, 0.f));
                float eh = ex2f(fminf(hh, 0.f));
                float ml = fmaxf(hl, 0.f);
                float mh = fmaxf(hh, 0.f);
                am[r] = fma2(pk(ml, mh), wv.x, am[r]);
                ae[r] = fma2(pk(el, eh), wv.y, ae[r]);
            }
            bv = bvn; gb = gbn; wv = wvn;
        }
    }

    const int gj = j0 + lane;
    const bool jint = (gj != 0) && (gj != NN - 1);
#pragma unroll
    for (int r = 0; r < 4; r++) {
        int gi = i0 + r0 + r;
        if (jint && gi != 0 && gi != NN - 1) {
            float a, b; unpk(add2(am[r], ae[r]), a, b);
            out[gi * NN + gj] = (a + b) + CADD;
        }
    }
}

// ---------------------------------------------------------------------------
extern "C" void kernel_launch(void* const* d_in, const int* in_sizes, int n_in,
                              void* d_out, int out_size)
{
    const float* xl    = (const float*)d_in[0];
    const float* xr    = (const float*)d_in[1];
    const float* W1    = (const float*)d_in[2];
    const float* b1    = (const float*)d_in[3];
    const float* gamma = (const float*)d_in[4];
    const float* beta  = (const float*)d_in[5];
    const float* W2    = (const float*)d_in[6];
    const float* b2    = (const float*)d_in[7];
    float* out = (float*)d_out;

    static bool attr_set = false;
    if (!attr_set) {
        cudaFuncSetAttribute(pair_fused_kernel,
                             cudaFuncAttributeMaxDynamicSharedMemorySize, SMEM_SZ);
        attr_set = true;
    }

    dim3 gpre(8, 12, 2);
    gemm_pre_kernel<<<gpre, 256>>>(xl, xr, W1);
    combine_kernel<<<NN, 256>>>(b1, W2);
    pair_fused_kernel<<<256 + 32, 256, SMEM_SZ>>>(gamma, beta, W2, b2, out);
}